// round 4
// baseline (speedup 1.0000x reference)
#include <cuda_runtime.h>

// B=16384, N=100000, D=128, F1=64, F2=32
// y[b] = dot(emb[x[b]], v) + Wo[F2 + x[b]] + c
//   u = W2^T @ Wo[0:32]  (64),  v = W1^T @ u  (128),  c = b1.u + b2.wo + bo
// Single launch; v/c recomputed per block (40KB weights, L1/L2-hot).
// 256-thread blocks keep regs/occupancy healthy so block overlap hides the
// per-block prep chain; gathers are issued before the prep loads.

#define THREADS 256
#define ROWS_PER_WARP 4
#define ROWS_PER_BLOCK (ROWS_PER_WARP * (THREADS / 32))  // 32

__global__ void __launch_bounds__(THREADS) wdl_fused_kernel(
    const int*   __restrict__ x,
    const float* __restrict__ emb,
    const float* __restrict__ W1,
    const float* __restrict__ b1,
    const float* __restrict__ W2,
    const float* __restrict__ b2,
    const float* __restrict__ Wo,
    const float* __restrict__ bo,
    float* __restrict__ out) {
    __shared__ float  su[64];
    __shared__ float4 sv[32];
    __shared__ float  sc;

    int t    = threadIdx.x;
    int lane = t & 31;
    int warp = t >> 5;
    int base = blockIdx.x * ROWS_PER_BLOCK + warp * ROWS_PER_WARP;

    // ---- issue the random gathers FIRST (4 independent rows per warp) ----
    int idxl = 0;
    if (lane < ROWS_PER_WARP) idxl = x[base + lane];
    int i0 = __shfl_sync(0xffffffff, idxl, 0);
    int i1 = __shfl_sync(0xffffffff, idxl, 1);
    int i2 = __shfl_sync(0xffffffff, idxl, 2);
    int i3 = __shfl_sync(0xffffffff, idxl, 3);

    const float4* E = reinterpret_cast<const float4*>(emb);
    float4 a0 = E[(long)i0 * 32 + lane];
    float4 a1 = E[(long)i1 * 32 + lane];
    float4 a2 = E[(long)i2 * 32 + lane];
    float4 a3 = E[(long)i3 * 32 + lane];
    float  wol = 0.f;
    if (lane < ROWS_PER_WARP) wol = Wo[32 + idxl];

    // ---- stage 1: u[64] by warps 0-1 (rolled-8 to cap registers) ----
    if (t < 64) {
        float s = 0.f;
        #pragma unroll 8
        for (int k = 0; k < 32; k++) s += W2[k * 64 + t] * Wo[k];
        su[t] = s;
    }
    __syncthreads();

    // ---- stage 2: v[128] by warps 0-3;  c by warp 0 (parallel shfl) ----
    if (t < 128) {
        float s = 0.f;
        #pragma unroll 8
        for (int j = 0; j < 64; j++) s += W1[j * 128 + t] * su[j];
        reinterpret_cast<float*>(sv)[t] = s;
    }
    if (warp == 0) {
        float cc = su[lane] * b1[lane] + su[lane + 32] * b1[lane + 32]
                 + b2[lane] * Wo[lane];
        #pragma unroll
        for (int off = 16; off; off >>= 1)
            cc += __shfl_xor_sync(0xffffffff, cc, off);
        if (lane == 0) sc = cc + bo[0];
    }
    __syncthreads();

    // ---- dot + reduce + store ----
    float4 b = sv[lane];
    float  c = sc;

    float s0 = a0.x * b.x + a0.y * b.y + a0.z * b.z + a0.w * b.w;
    float s1 = a1.x * b.x + a1.y * b.y + a1.z * b.z + a1.w * b.w;
    float s2 = a2.x * b.x + a2.y * b.y + a2.z * b.z + a2.w * b.w;
    float s3 = a3.x * b.x + a3.y * b.y + a3.z * b.z + a3.w * b.w;

    #pragma unroll
    for (int off = 16; off; off >>= 1) {
        s0 += __shfl_xor_sync(0xffffffff, s0, off);
        s1 += __shfl_xor_sync(0xffffffff, s1, off);
        s2 += __shfl_xor_sync(0xffffffff, s2, off);
        s3 += __shfl_xor_sync(0xffffffff, s3, off);
    }

    if (lane < ROWS_PER_WARP) {
        float sv_ = (lane == 0) ? s0 : (lane == 1) ? s1 : (lane == 2) ? s2 : s3;
        out[base + lane] = sv_ + wol + c;
    }
}

extern "C" void kernel_launch(void* const* d_in, const int* in_sizes, int n_in,
                              void* d_out, int out_size) {
    const int*   x   = (const int*)d_in[0];
    const float* emb = (const float*)d_in[1];
    const float* W1  = (const float*)d_in[2];
    const float* b1  = (const float*)d_in[3];
    const float* W2  = (const float*)d_in[4];
    const float* b2  = (const float*)d_in[5];
    const float* Wo  = (const float*)d_in[6];
    const float* bo  = (const float*)d_in[7];
    float* out = (float*)d_out;

    const int B = in_sizes[0];  // 16384
    wdl_fused_kernel<<<B / ROWS_PER_BLOCK, THREADS>>>(x, emb, W1, b1, W2, b2, Wo, bo, out);
}